// round 16
// baseline (speedup 1.0000x reference)
#include <cuda_runtime.h>
#include <cuda_fp16.h>
#include <cstdint>

#define D_DIM 1024
#define K_TOP 307
#define MAX_N 65536

// ============================ PTX helpers ===================================
__device__ __forceinline__ uint32_t smem_u32(const void* p) {
    uint32_t a;
    asm("{ .reg .u64 t; cvta.to.shared.u64 t, %1; cvt.u32.u64 %0, t; }" : "=r"(a) : "l"(p));
    return a;
}
#define CPA16(saddr, gptr) \
    asm volatile("cp.async.cg.shared.global [%0], [%1], 16;" :: "r"(saddr), "l"(gptr) : "memory")
#define CP_COMMIT() asm volatile("cp.async.commit_group;" ::: "memory")
#define CP_WAIT2()  asm volatile("cp.async.wait_group 2;" ::: "memory")
#define CP_WAIT1()  asm volatile("cp.async.wait_group 1;" ::: "memory")
#define CP_WAIT0()  asm volatile("cp.async.wait_group 0;" ::: "memory")

#define LDSM_X4(r0, r1, r2, r3, addr) \
    asm volatile("ldmatrix.sync.aligned.m8n8.x4.shared.b16 {%0,%1,%2,%3}, [%4];" \
        : "=r"(r0), "=r"(r1), "=r"(r2), "=r"(r3) : "r"(addr))

#define MMA16816F16(d, a, b0, b1) \
    asm volatile("mma.sync.aligned.m16n8k16.row.col.f32.f16.f16.f32 " \
        "{%0,%1,%2,%3}, {%4,%5,%6,%7}, {%8,%9}, {%0,%1,%2,%3};" \
        : "+f"((d)[0]), "+f"((d)[1]), "+f"((d)[2]), "+f"((d)[3]) \
        : "r"((a)[0]), "r"((a)[1]), "r"((a)[2]), "r"((a)[3]), "r"(b0), "r"(b1))

// ============================ numeric helpers ================================
__device__ __forceinline__ float sigmoid_acc(float z) {
    float x = -z;
    x = fminf(fmaxf(x, -87.0f), 87.0f);
    float t = x * 1.4426950408889634f;
    float n = rintf(t);
    float r = fmaf(n, -0.693145751953125f, x);
    r = fmaf(n, -1.42860676533018687e-06f, r);
    float p = 1.9875691500e-4f;
    p = fmaf(p, r, 1.3981999507e-3f);
    p = fmaf(p, r, 8.3333331174e-3f);
    p = fmaf(p, r, 4.1665795894e-2f);
    p = fmaf(p, r, 1.6666665459e-1f);
    p = fmaf(p, r, 5.0000001201e-1f);
    float y = fmaf(r * r, p, r) + 1.0f;
    int   i  = (int)n;
    float sc = __int_as_float((i + 127) << 23);
    return 1.0f / (1.0f + y * sc);
}

// ============================ pre-split storage ==============================
__device__ __align__(16) uint16_t g_Wh[D_DIM * D_DIM];
__device__ __align__(16) uint16_t g_Xh[(size_t)MAX_N * D_DIM];

__global__ __launch_bounds__(256)
void split1_kernel(const float* __restrict__ src, uint16_t* __restrict__ oh) {
    size_t gid = (size_t)blockIdx.x * 256 + threadIdx.x;  // one 8-float group
    float4 a = ((const float4*)src)[2 * gid];
    float4 c = ((const float4*)src)[2 * gid + 1];
    float v[8] = {a.x, a.y, a.z, a.w, c.x, c.y, c.z, c.w};
    uint16_t h[8];
#pragma unroll
    for (int i = 0; i < 8; i++) h[i] = __half_as_ushort(__float2half_rn(v[i]));
    uint4 H = {(uint32_t)h[0] | ((uint32_t)h[1] << 16), (uint32_t)h[2] | ((uint32_t)h[3] << 16),
               (uint32_t)h[4] | ((uint32_t)h[5] << 16), (uint32_t)h[6] | ((uint32_t)h[7] << 16)};
    ((uint4*)oh)[gid] = H;
}

// ============================ GEMM (single-product HMMA) =====================
#define ATILE   8192                    // 64 x 64 fp16
#define BTILE   16384                   // 128 x 64 fp16
#define BOFF    ATILE
#define STAGE_B (ATILE + BTILE)         // 24576
#define NSTAGE  4
#define SMEM_GEMM (NSTAGE * STAGE_B)    // 98304
#define NCHUNK  (D_DIM / 64)            // 16

__global__ __launch_bounds__(256, 2)
void gemm_hmma_kernel(const float* __restrict__ bias, float* __restrict__ S) {
    extern __shared__ char smem[];
    const uint32_t sb = smem_u32(smem);
    const int tid  = threadIdx.x;
    const int lane = tid & 31;
    const int wid  = tid >> 5;
    const int mg   = wid >> 2;
    const int ng   = wid & 3;
    const int brow = blockIdx.y << 6;
    const int bcol = blockIdx.x << 7;

#define ISSUE_STAGE(c)                                                        \
    do {                                                                      \
        const int k0_ = (c) * 64;                                             \
        const uint32_t st_ = sb + ((c) & (NSTAGE - 1)) * STAGE_B;             \
        _Pragma("unroll")                                                     \
        for (int j = 0; j < 2; j++) {                                         \
            int g = tid + j * 256;                                            \
            int row = g >> 3, cc = g & 7;                                     \
            uint32_t sw = (uint32_t)(row * 128 + ((cc ^ (row & 7)) << 4));    \
            size_t ga = (size_t)(brow + row) * D_DIM + k0_ + cc * 8;          \
            CPA16(st_ + sw, g_Xh + ga);                                       \
        }                                                                     \
        _Pragma("unroll")                                                     \
        for (int j = 0; j < 4; j++) {                                         \
            int g = tid + j * 256;                                            \
            int row = g >> 3, cc = g & 7;                                     \
            uint32_t sw = (uint32_t)(row * 128 + ((cc ^ (row & 7)) << 4));    \
            size_t gb = (size_t)(bcol + row) * D_DIM + k0_ + cc * 8;          \
            CPA16(st_ + BOFF + sw, g_Wh + gb);                                \
        }                                                                     \
        CP_COMMIT();                                                          \
    } while (0)

    const int aRow = mg * 32 + (((lane >> 3) & 1) << 3) + (lane & 7);
    const int aC   = (lane >> 4);
    const uint32_t aRB = (uint32_t)(aRow * 128);
    const int aXor = aRow & 7;
    const int bRow = ng * 32 + (((lane >> 4) & 1) << 3) + (lane & 7);
    const int bC   = (lane >> 3) & 1;
    const uint32_t bRB = (uint32_t)(bRow * 128);
    const int bXor = bRow & 7;

#define LOAD_FRAGS(q, ks, stA_, stB_)                                          \
    do {                                                                       \
        _Pragma("unroll")                                                      \
        for (int mt = 0; mt < 2; mt++) {                                       \
            uint32_t addr = (stA_) + aRB + mt * 2048 +                         \
                            (uint32_t)(((aC + 2 * (ks)) ^ aXor) << 4);         \
            LDSM_X4(fa[q][mt][0], fa[q][mt][1], fa[q][mt][2], fa[q][mt][3], addr); \
        }                                                                      \
        _Pragma("unroll")                                                      \
        for (int np = 0; np < 2; np++) {                                       \
            uint32_t addr = (stB_) + bRB + np * 2048 +                         \
                            (uint32_t)(((bC + 2 * (ks)) ^ bXor) << 4);         \
            LDSM_X4(fb[q][np][0], fb[q][np][1], fb[q][np][2], fb[q][np][3], addr); \
        }                                                                      \
    } while (0)

    float tot[2][4][4];
    float ah[2][4][4];
    uint32_t fa[2][2][4];
    uint32_t fb[2][2][4];
#pragma unroll
    for (int mt = 0; mt < 2; mt++)
#pragma unroll
        for (int nt = 0; nt < 4; nt++)
#pragma unroll
            for (int e = 0; e < 4; e++) tot[mt][nt][e] = 0.0f;

    ISSUE_STAGE(0);
    ISSUE_STAGE(1);

    for (int c = 0; c < NCHUNK; ++c) {
        if (c + 2 < NCHUNK) {
            ISSUE_STAGE(c + 2);
            CP_WAIT2();
        } else if (c == NCHUNK - 2) {
            CP_WAIT1();
        } else {
            CP_WAIT0();
        }
        __syncthreads();

        const uint32_t stA = sb + (c & (NSTAGE - 1)) * STAGE_B;
        const uint32_t stB = stA + BOFF;

#pragma unroll
        for (int mt = 0; mt < 2; mt++)
#pragma unroll
            for (int nt = 0; nt < 4; nt++)
#pragma unroll
                for (int e = 0; e < 4; e++) ah[mt][nt][e] = 0.0f;

        LOAD_FRAGS(0, 0, stA, stB);

#pragma unroll
        for (int ks = 0; ks < 4; ++ks) {
            const int q = ks & 1;
            if (ks < 3) LOAD_FRAGS((ks + 1) & 1, ks + 1, stA, stB);
#pragma unroll
            for (int mt = 0; mt < 2; mt++)
#pragma unroll
                for (int np = 0; np < 2; np++) {
                    MMA16816F16(ah[mt][2 * np + 0], fa[q][mt], fb[q][np][0], fb[q][np][1]);
                    MMA16816F16(ah[mt][2 * np + 1], fa[q][mt], fb[q][np][2], fb[q][np][3]);
                }
        }
#pragma unroll
        for (int mt = 0; mt < 2; mt++)
#pragma unroll
            for (int nt = 0; nt < 4; nt++)
#pragma unroll
                for (int e = 0; e < 4; e++) tot[mt][nt][e] += ah[mt][nt][e];
    }

#pragma unroll
    for (int mt = 0; mt < 2; mt++) {
        const int m0 = brow + mg * 32 + mt * 16 + (lane >> 2);
#pragma unroll
        for (int nt = 0; nt < 4; nt++) {
            const int n0 = bcol + ng * 32 + nt * 8 + 2 * (lane & 3);
            const float2 bb = *(const float2*)&bias[n0];
            float2 o0, o1;
            o0.x = sigmoid_acc(tot[mt][nt][0] + bb.x);
            o0.y = sigmoid_acc(tot[mt][nt][1] + bb.y);
            o1.x = sigmoid_acc(tot[mt][nt][2] + bb.x);
            o1.y = sigmoid_acc(tot[mt][nt][3] + bb.y);
            *(float2*)&S[(size_t)m0 * D_DIM + n0]       = o0;
            *(float2*)&S[(size_t)(m0 + 8) * D_DIM + n0] = o1;
        }
    }
}

// ============================ top-k with exact boundary rescue ===============
#define MARGIN 6.0e-4f
#define CMAX   64

// One radix pass: warp-aggregated histogram atomics (match_any), 3 barriers,
// no sscan array (neighbor ge via shfl; cross-warp boundary = own `add`).
// Leaves hist[] zeroed for the next pass.
__device__ __forceinline__ void radix_pass(
    const uint32_t* vv, int shift, uint32_t dm,
    uint32_t& prefix, int& need,
    int* hist, int* wsum, uint32_t* sh_pref, int* sh_need,
    int lane, int wrp)
{
#pragma unroll
    for (int k = 0; k < 4; k++) {
        const bool cond = ((vv[k] & dm) == prefix);
        const unsigned m = __ballot_sync(0xffffffffu, cond);
        if (cond) {
            const unsigned d = (vv[k] >> shift) & 255u;
            const unsigned peers = __match_any_sync(m, d);
            if ((int)(__ffs(peers) - 1) == lane)
                atomicAdd(&hist[d], (int)__popc(peers));
        }
    }
    __syncthreads();                      // atomics complete
    const int t = (wrp << 5) + lane;
    int s = hist[t];
    hist[t] = 0;                          // pre-zero for next pass
#pragma unroll
    for (int off = 1; off < 32; off <<= 1) {
        int v = __shfl_down_sync(0xffffffffu, s, off);
        if (lane + off < 32) s += v;
    }
    if (lane == 0) wsum[wrp] = s;
    __syncthreads();
    int add = 0;
#pragma unroll
    for (int w2 = 0; w2 < 8; w2++) add += (w2 > wrp) ? wsum[w2] : 0;
    const int ge = s + add;               // # candidates with digit >= t
    int nxt = __shfl_down_sync(0xffffffffu, ge, 1);
    if (lane == 31) nxt = add;            // ge[t+1] across warp boundary
    if (ge >= need && nxt < need) {
        *sh_pref = prefix | ((uint32_t)t << shift);
        *sh_need = need - nxt;
    }
    __syncthreads();
    prefix = *sh_pref;
    need   = *sh_need;
}

__global__ __launch_bounds__(256, 8)
void topk_mask_kernel(const float* __restrict__ X, const float* __restrict__ S,
                      const float* __restrict__ W, const float* __restrict__ bias,
                      float* __restrict__ O) {
    const int row = blockIdx.x;
    const int t   = threadIdx.x;
    const int lane = t & 31, wrp = t >> 5;
    const size_t base = (size_t)row * D_DIM;

    const uint4 u = ((const uint4*)(S + base))[t];
    const float4 xv = ((const float4*)(X + base))[t];
    const uint32_t vv[4] = {u.x, u.y, u.z, u.w};

    __shared__ int hist[256];
    __shared__ int wsum[8];
    __shared__ uint32_t sh_pref;
    __shared__ int sh_need;
    __shared__ int ccount;
    __shared__ uint32_t candv[CMAX];
    __shared__ uint32_t sh_T;
    __shared__ float xs[D_DIM];
    __shared__ int wcount;
    __shared__ int sh_csure;
    __shared__ uint16_t wci[CMAX];
    __shared__ float wcf[CMAX];
    __shared__ uint32_t selbmp[32];

    *(float4*)&xs[4 * t] = xv;
    hist[t] = 0;
    if (t < 32) selbmp[t] = 0;
    if (t == 0) { ccount = 0; wcount = 0; }
    __syncthreads();

    uint32_t prefix = 0;
    int need = K_TOP;

    radix_pass(vv, 24, 0u,          prefix, need, hist, wsum, &sh_pref, &sh_need, lane, wrp);
    radix_pass(vv, 16, 0xFF000000u, prefix, need, hist, wsum, &sh_pref, &sh_need, lane, wrp);

    // ---- exact T (K-th largest approx score) ----
    const uint32_t p16 = prefix;
#pragma unroll
    for (int k = 0; k < 4; k++) {
        if ((vv[k] & 0xFFFF0000u) == p16) {
            int pos = atomicAdd(&ccount, 1);
            if (pos < CMAX) candv[pos] = vv[k];
        }
    }
    __syncthreads();
    if (ccount <= CMAX) {
        if (t < ccount) {
            const uint32_t v = candv[t];
            int rs = 0, eq = 0;
            for (int j = 0; j < ccount; j++) { rs += candv[j] > v; eq += candv[j] == v; }
            if (rs < need && rs + eq >= need) sh_T = v;
        }
        __syncthreads();
    } else {
        // fallback: finish radix passes 2,3 -> exact K-th value (rare)
        radix_pass(vv, 8, 0xFFFF0000u, prefix, need, hist, wsum, &sh_pref, &sh_need, lane, wrp);
        radix_pass(vv, 0, 0xFFFFFF00u, prefix, need, hist, wsum, &sh_pref, &sh_need, lane, wrp);
        if (t == 0) sh_T = prefix;
        __syncthreads();
    }

    const float Tf = __uint_as_float(sh_T);
    const float hi = Tf + MARGIN;
    const float lo = Tf - MARGIN;
    const float sf[4] = {__uint_as_float(u.x), __uint_as_float(u.y),
                         __uint_as_float(u.z), __uint_as_float(u.w)};

    // ---- sure-in count + window gather (single region) ----
    const int idx0 = t << 2;
    {
        int cs = (sf[0] > hi) + (sf[1] > hi) + (sf[2] > hi) + (sf[3] > hi);
#pragma unroll
        for (int off = 16; off; off >>= 1) cs += __shfl_down_sync(0xffffffffu, cs, off);
        if (lane == 0) wsum[wrp] = cs;
#pragma unroll
        for (int k = 0; k < 4; k++) {
            if (sf[k] >= lo && sf[k] <= hi) {
                int pos = atomicAdd(&wcount, 1);
                if (pos < CMAX) wci[pos] = (uint16_t)(idx0 + k);
            }
        }
        __syncthreads();
        if (t == 0) {
            int tt = 0;
#pragma unroll
            for (int i = 0; i < 8; i++) tt += wsum[i];
            sh_csure = tt;
        }
        __syncthreads();
    }
    const int need2 = K_TOP - sh_csure;
    const int wcnt  = (wcount <= CMAX) ? wcount : CMAX;
    const bool overflow = wcount > CMAX;

    // ---- exact fp32 rescoring: one warp per candidate, float4 x 4 chains ----
    if (!overflow) {
        for (int c = wrp; c < wcnt; c += 8) {
            const int e = wci[c];
            const float4* wr = (const float4*)(W + (size_t)e * D_DIM);
            float a0 = 0.0f, a1 = 0.0f, a2 = 0.0f, a3 = 0.0f;
#pragma unroll
            for (int j = 0; j < 8; j++) {
                const int i4 = j * 32 + lane;
                const float4 wv = wr[i4];
                const float4 xq = *(const float4*)&xs[4 * i4];
                a0 = fmaf(xq.x, wv.x, a0);
                a1 = fmaf(xq.y, wv.y, a1);
                a2 = fmaf(xq.z, wv.z, a2);
                a3 = fmaf(xq.w, wv.w, a3);
            }
            float acc = (a0 + a1) + (a2 + a3);
#pragma unroll
            for (int off = 16; off; off >>= 1) acc += __shfl_down_sync(0xffffffffu, acc, off);
            if (lane == 0) wcf[c] = sigmoid_acc(acc + bias[e]);
        }
        __syncthreads();
        if (t < wcnt) {
            const float f = wcf[t];
            const int   id = wci[t];
            int r = 0;
            for (int j = 0; j < wcnt; j++) {
                const float fj = wcf[j];
                r += (fj > f) || (fj == f && wci[j] < id);
            }
            if (r < need2) atomicOr(&selbmp[id >> 5], 1u << (id & 31));
        }
        __syncthreads();
    }

    // ---- write masked output ----
    float4 o;
    if (!overflow) {
        const bool s0 = (sf[0] > hi) || (sf[0] >= lo && ((selbmp[(idx0 + 0) >> 5] >> ((idx0 + 0) & 31)) & 1u));
        const bool s1 = (sf[1] > hi) || (sf[1] >= lo && ((selbmp[(idx0 + 1) >> 5] >> ((idx0 + 1) & 31)) & 1u));
        const bool s2 = (sf[2] > hi) || (sf[2] >= lo && ((selbmp[(idx0 + 2) >> 5] >> ((idx0 + 2) & 31)) & 1u));
        const bool s3 = (sf[3] > hi) || (sf[3] >= lo && ((selbmp[(idx0 + 3) >> 5] >> ((idx0 + 3) & 31)) & 1u));
        o.x = s0 ? xv.x : 0.0f;
        o.y = s1 ? xv.y : 0.0f;
        o.z = s2 ? xv.z : 0.0f;
        o.w = s3 ? xv.w : 0.0f;
    } else {
        o.x = (sf[0] >= Tf) ? xv.x : 0.0f;
        o.y = (sf[1] >= Tf) ? xv.y : 0.0f;
        o.z = (sf[2] >= Tf) ? xv.z : 0.0f;
        o.w = (sf[3] >= Tf) ? xv.w : 0.0f;
    }
    ((float4*)(O + base))[t] = o;
}

// ============================ launch =========================================
extern "C" void kernel_launch(void* const* d_in, const int* in_sizes, int n_in,
                              void* d_out, int out_size) {
    const float* X = (const float*)d_in[0];  // [N, 1024]
    const float* W = (const float*)d_in[1];  // [1024, 1024]
    const float* b = (const float*)d_in[2];  // [1024]
    float* out = (float*)d_out;              // [2, N, 1024]

    const int N = in_sizes[0] / D_DIM;
    float* S = out + (size_t)N * D_DIM;

    uint16_t *wh, *xh;
    cudaGetSymbolAddress((void**)&wh, g_Wh);
    cudaGetSymbolAddress((void**)&xh, g_Xh);

    cudaFuncSetAttribute(gemm_hmma_kernel,
                         cudaFuncAttributeMaxDynamicSharedMemorySize, SMEM_GEMM);

    split1_kernel<<<D_DIM * D_DIM / 8 / 256, 256>>>(W, wh);
    split1_kernel<<<(int)((size_t)N * D_DIM / 8 / 256), 256>>>(X, xh);
    gemm_hmma_kernel<<<dim3(D_DIM / 128, N / 64), 256, SMEM_GEMM>>>(b, S);
    topk_mask_kernel<<<N, 256>>>(X, S, W, b, out);
}

// round 17
// speedup vs baseline: 1.2076x; 1.2076x over previous
#include <cuda_runtime.h>
#include <cuda_fp16.h>
#include <cstdint>

#define D_DIM 1024
#define K_TOP 307
#define MAX_N 65536

// ============================ PTX helpers ===================================
__device__ __forceinline__ uint32_t smem_u32(const void* p) {
    uint32_t a;
    asm("{ .reg .u64 t; cvta.to.shared.u64 t, %1; cvt.u32.u64 %0, t; }" : "=r"(a) : "l"(p));
    return a;
}
#define CPA16(saddr, gptr) \
    asm volatile("cp.async.cg.shared.global [%0], [%1], 16;" :: "r"(saddr), "l"(gptr) : "memory")
#define CP_COMMIT() asm volatile("cp.async.commit_group;" ::: "memory")
#define CP_WAIT2()  asm volatile("cp.async.wait_group 2;" ::: "memory")
#define CP_WAIT1()  asm volatile("cp.async.wait_group 1;" ::: "memory")
#define CP_WAIT0()  asm volatile("cp.async.wait_group 0;" ::: "memory")

#define LDSM_X4(r0, r1, r2, r3, addr) \
    asm volatile("ldmatrix.sync.aligned.m8n8.x4.shared.b16 {%0,%1,%2,%3}, [%4];" \
        : "=r"(r0), "=r"(r1), "=r"(r2), "=r"(r3) : "r"(addr))

#define MMA16816F16(d, a, b0, b1) \
    asm volatile("mma.sync.aligned.m16n8k16.row.col.f32.f16.f16.f32 " \
        "{%0,%1,%2,%3}, {%4,%5,%6,%7}, {%8,%9}, {%0,%1,%2,%3};" \
        : "+f"((d)[0]), "+f"((d)[1]), "+f"((d)[2]), "+f"((d)[3]) \
        : "r"((a)[0]), "r"((a)[1]), "r"((a)[2]), "r"((a)[3]), "r"(b0), "r"(b1))

// ============================ numeric helpers ================================
__device__ __forceinline__ float sigmoid_acc(float z) {
    float x = -z;
    x = fminf(fmaxf(x, -87.0f), 87.0f);
    float t = x * 1.4426950408889634f;
    float n = rintf(t);
    float r = fmaf(n, -0.693145751953125f, x);
    r = fmaf(n, -1.42860676533018687e-06f, r);
    float p = 1.9875691500e-4f;
    p = fmaf(p, r, 1.3981999507e-3f);
    p = fmaf(p, r, 8.3333331174e-3f);
    p = fmaf(p, r, 4.1665795894e-2f);
    p = fmaf(p, r, 1.6666665459e-1f);
    p = fmaf(p, r, 5.0000001201e-1f);
    float y = fmaf(r * r, p, r) + 1.0f;
    int   i  = (int)n;
    float sc = __int_as_float((i + 127) << 23);
    return 1.0f / (1.0f + y * sc);
}

// ============================ pre-split storage ==============================
__device__ __align__(16) uint16_t g_Wh[D_DIM * D_DIM];
__device__ __align__(16) uint16_t g_Xh[(size_t)MAX_N * D_DIM];
// rescue scratch
#define SLOTS 32
__device__ int      g_cnt[MAX_N];
__device__ int      g_need2[MAX_N];
__device__ uint16_t g_cand[(size_t)MAX_N * SLOTS];

__global__ __launch_bounds__(256)
void split1_kernel(const float* __restrict__ src, uint16_t* __restrict__ oh) {
    size_t gid = (size_t)blockIdx.x * 256 + threadIdx.x;  // one 8-float group
    float4 a = ((const float4*)src)[2 * gid];
    float4 c = ((const float4*)src)[2 * gid + 1];
    float v[8] = {a.x, a.y, a.z, a.w, c.x, c.y, c.z, c.w};
    uint16_t h[8];
#pragma unroll
    for (int i = 0; i < 8; i++) h[i] = __half_as_ushort(__float2half_rn(v[i]));
    uint4 H = {(uint32_t)h[0] | ((uint32_t)h[1] << 16), (uint32_t)h[2] | ((uint32_t)h[3] << 16),
               (uint32_t)h[4] | ((uint32_t)h[5] << 16), (uint32_t)h[6] | ((uint32_t)h[7] << 16)};
    ((uint4*)oh)[gid] = H;
}

// ============================ GEMM (single-product HMMA) =====================
#define ATILE   8192                    // 64 x 64 fp16
#define BTILE   16384                   // 128 x 64 fp16
#define BOFF    ATILE
#define STAGE_B (ATILE + BTILE)         // 24576
#define NSTAGE  4
#define SMEM_GEMM (NSTAGE * STAGE_B)    // 98304
#define NCHUNK  (D_DIM / 64)            // 16

__global__ __launch_bounds__(256, 2)
void gemm_hmma_kernel(const float* __restrict__ bias, float* __restrict__ S) {
    extern __shared__ char smem[];
    const uint32_t sb = smem_u32(smem);
    const int tid  = threadIdx.x;
    const int lane = tid & 31;
    const int wid  = tid >> 5;
    const int mg   = wid >> 2;
    const int ng   = wid & 3;
    const int brow = blockIdx.y << 6;
    const int bcol = blockIdx.x << 7;

#define ISSUE_STAGE(c)                                                        \
    do {                                                                      \
        const int k0_ = (c) * 64;                                             \
        const uint32_t st_ = sb + ((c) & (NSTAGE - 1)) * STAGE_B;             \
        _Pragma("unroll")                                                     \
        for (int j = 0; j < 2; j++) {                                         \
            int g = tid + j * 256;                                            \
            int row = g >> 3, cc = g & 7;                                     \
            uint32_t sw = (uint32_t)(row * 128 + ((cc ^ (row & 7)) << 4));    \
            size_t ga = (size_t)(brow + row) * D_DIM + k0_ + cc * 8;          \
            CPA16(st_ + sw, g_Xh + ga);                                       \
        }                                                                     \
        _Pragma("unroll")                                                     \
        for (int j = 0; j < 4; j++) {                                         \
            int g = tid + j * 256;                                            \
            int row = g >> 3, cc = g & 7;                                     \
            uint32_t sw = (uint32_t)(row * 128 + ((cc ^ (row & 7)) << 4));    \
            size_t gb = (size_t)(bcol + row) * D_DIM + k0_ + cc * 8;          \
            CPA16(st_ + BOFF + sw, g_Wh + gb);                                \
        }                                                                     \
        CP_COMMIT();                                                          \
    } while (0)

    const int aRow = mg * 32 + (((lane >> 3) & 1) << 3) + (lane & 7);
    const int aC   = (lane >> 4);
    const uint32_t aRB = (uint32_t)(aRow * 128);
    const int aXor = aRow & 7;
    const int bRow = ng * 32 + (((lane >> 4) & 1) << 3) + (lane & 7);
    const int bC   = (lane >> 3) & 1;
    const uint32_t bRB = (uint32_t)(bRow * 128);
    const int bXor = bRow & 7;

#define LOAD_FRAGS(q, ks, stA_, stB_)                                          \
    do {                                                                       \
        _Pragma("unroll")                                                      \
        for (int mt = 0; mt < 2; mt++) {                                       \
            uint32_t addr = (stA_) + aRB + mt * 2048 +                         \
                            (uint32_t)(((aC + 2 * (ks)) ^ aXor) << 4);         \
            LDSM_X4(fa[q][mt][0], fa[q][mt][1], fa[q][mt][2], fa[q][mt][3], addr); \
        }                                                                      \
        _Pragma("unroll")                                                      \
        for (int np = 0; np < 2; np++) {                                       \
            uint32_t addr = (stB_) + bRB + np * 2048 +                         \
                            (uint32_t)(((bC + 2 * (ks)) ^ bXor) << 4);         \
            LDSM_X4(fb[q][np][0], fb[q][np][1], fb[q][np][2], fb[q][np][3], addr); \
        }                                                                      \
    } while (0)

    float tot[2][4][4];
    float ah[2][4][4];
    uint32_t fa[2][2][4];
    uint32_t fb[2][2][4];
#pragma unroll
    for (int mt = 0; mt < 2; mt++)
#pragma unroll
        for (int nt = 0; nt < 4; nt++)
#pragma unroll
            for (int e = 0; e < 4; e++) tot[mt][nt][e] = 0.0f;

    ISSUE_STAGE(0);
    ISSUE_STAGE(1);

    for (int c = 0; c < NCHUNK; ++c) {
        if (c + 2 < NCHUNK) {
            ISSUE_STAGE(c + 2);
            CP_WAIT2();
        } else if (c == NCHUNK - 2) {
            CP_WAIT1();
        } else {
            CP_WAIT0();
        }
        __syncthreads();

        const uint32_t stA = sb + (c & (NSTAGE - 1)) * STAGE_B;
        const uint32_t stB = stA + BOFF;

#pragma unroll
        for (int mt = 0; mt < 2; mt++)
#pragma unroll
            for (int nt = 0; nt < 4; nt++)
#pragma unroll
                for (int e = 0; e < 4; e++) ah[mt][nt][e] = 0.0f;

        LOAD_FRAGS(0, 0, stA, stB);

#pragma unroll
        for (int ks = 0; ks < 4; ++ks) {
            const int q = ks & 1;
            if (ks < 3) LOAD_FRAGS((ks + 1) & 1, ks + 1, stA, stB);
#pragma unroll
            for (int mt = 0; mt < 2; mt++)
#pragma unroll
                for (int np = 0; np < 2; np++) {
                    MMA16816F16(ah[mt][2 * np + 0], fa[q][mt], fb[q][np][0], fb[q][np][1]);
                    MMA16816F16(ah[mt][2 * np + 1], fa[q][mt], fb[q][np][2], fb[q][np][3]);
                }
        }
#pragma unroll
        for (int mt = 0; mt < 2; mt++)
#pragma unroll
            for (int nt = 0; nt < 4; nt++)
#pragma unroll
                for (int e = 0; e < 4; e++) tot[mt][nt][e] += ah[mt][nt][e];
    }

#pragma unroll
    for (int mt = 0; mt < 2; mt++) {
        const int m0 = brow + mg * 32 + mt * 16 + (lane >> 2);
#pragma unroll
        for (int nt = 0; nt < 4; nt++) {
            const int n0 = bcol + ng * 32 + nt * 8 + 2 * (lane & 3);
            const float2 bb = *(const float2*)&bias[n0];
            float2 o0, o1;
            o0.x = sigmoid_acc(tot[mt][nt][0] + bb.x);
            o0.y = sigmoid_acc(tot[mt][nt][1] + bb.y);
            o1.x = sigmoid_acc(tot[mt][nt][2] + bb.x);
            o1.y = sigmoid_acc(tot[mt][nt][3] + bb.y);
            *(float2*)&S[(size_t)m0 * D_DIM + n0]       = o0;
            *(float2*)&S[(size_t)(m0 + 8) * D_DIM + n0] = o1;
        }
    }
}

// ============================ kernel 1: select ===============================
// Round-11-shaped radix select + sure/window classification. Writes O with
// sure-ins set, window positions zeroed; emits window candidates + need2.
#define MARGIN 6.0e-4f
#define CMAX   64

__device__ __forceinline__ void radix_pass_plain(
    const uint32_t* vv, int shift, uint32_t dm,
    uint32_t& prefix, int& need,
    int* hist, int* sscan, int* wsum, uint32_t* sh_pref, int* sh_need,
    int t, int lane, int wrp)
{
    hist[t] = 0;
    __syncthreads();
    if ((vv[0] & dm) == prefix) atomicAdd(&hist[(vv[0] >> shift) & 255], 1);
    if ((vv[1] & dm) == prefix) atomicAdd(&hist[(vv[1] >> shift) & 255], 1);
    if ((vv[2] & dm) == prefix) atomicAdd(&hist[(vv[2] >> shift) & 255], 1);
    if ((vv[3] & dm) == prefix) atomicAdd(&hist[(vv[3] >> shift) & 255], 1);
    __syncthreads();
    int s = hist[t];
#pragma unroll
    for (int off = 1; off < 32; off <<= 1) {
        int v = __shfl_down_sync(0xffffffffu, s, off);
        if (lane + off < 32) s += v;
    }
    if (lane == 0) wsum[wrp] = s;
    __syncthreads();
    int add = 0;
#pragma unroll
    for (int w2 = 0; w2 < 8; w2++) add += (w2 > wrp) ? wsum[w2] : 0;
    const int ge = s + add;
    sscan[t] = ge;
    __syncthreads();
    const int nxt = (t < 255) ? sscan[t + 1] : 0;
    if (ge >= need && nxt < need) {
        *sh_pref = prefix | ((uint32_t)t << shift);
        *sh_need = need - nxt;
    }
    __syncthreads();
    prefix = *sh_pref;
    need   = *sh_need;
}

__global__ __launch_bounds__(256, 8)
void topk_select_kernel(const float* __restrict__ X, const float* __restrict__ S,
                        float* __restrict__ O) {
    const int row = blockIdx.x;
    const int t   = threadIdx.x;
    const int lane = t & 31, wrp = t >> 5;
    const size_t base = (size_t)row * D_DIM;

    const uint4 u = ((const uint4*)(S + base))[t];
    const float4 xv = ((const float4*)(X + base))[t];
    const uint32_t vv[4] = {u.x, u.y, u.z, u.w};

    __shared__ int hist[256];
    __shared__ int sscan[256];
    __shared__ int wsum[8];
    __shared__ uint32_t sh_pref;
    __shared__ int sh_need;
    __shared__ int ccount;
    __shared__ uint32_t candv[CMAX];
    __shared__ uint32_t sh_T;
    __shared__ int wcount;
    __shared__ int sh_csure;

    if (t == 0) { ccount = 0; wcount = 0; }

    uint32_t prefix = 0;
    int need = K_TOP;

    radix_pass_plain(vv, 24, 0u,          prefix, need, hist, sscan, wsum, &sh_pref, &sh_need, t, lane, wrp);
    radix_pass_plain(vv, 16, 0xFF000000u, prefix, need, hist, sscan, wsum, &sh_pref, &sh_need, t, lane, wrp);

    // ---- exact T (K-th largest approx score) ----
    const uint32_t p16 = prefix;
#pragma unroll
    for (int k = 0; k < 4; k++) {
        if ((vv[k] & 0xFFFF0000u) == p16) {
            int pos = atomicAdd(&ccount, 1);
            if (pos < CMAX) candv[pos] = vv[k];
        }
    }
    __syncthreads();
    if (ccount <= CMAX) {
        if (t < ccount) {
            const uint32_t v = candv[t];
            int rs = 0, eq = 0;
            for (int j = 0; j < ccount; j++) { rs += candv[j] > v; eq += candv[j] == v; }
            if (rs < need && rs + eq >= need) sh_T = v;
        }
        __syncthreads();
    } else {
        radix_pass_plain(vv, 8, 0xFFFF0000u, prefix, need, hist, sscan, wsum, &sh_pref, &sh_need, t, lane, wrp);
        radix_pass_plain(vv, 0, 0xFFFFFF00u, prefix, need, hist, sscan, wsum, &sh_pref, &sh_need, t, lane, wrp);
        if (t == 0) sh_T = prefix;
        __syncthreads();
    }

    const float Tf = __uint_as_float(sh_T);
    const float hi = Tf + MARGIN;
    const float lo = Tf - MARGIN;
    const float sf[4] = {__uint_as_float(u.x), __uint_as_float(u.y),
                         __uint_as_float(u.z), __uint_as_float(u.w)};
    const int idx0 = t << 2;

    // ---- sure-in count + window gather to GLOBAL slots ----
    {
        int cs = (sf[0] > hi) + (sf[1] > hi) + (sf[2] > hi) + (sf[3] > hi);
#pragma unroll
        for (int off = 16; off; off >>= 1) cs += __shfl_down_sync(0xffffffffu, cs, off);
        if (lane == 0) wsum[wrp] = cs;
#pragma unroll
        for (int k = 0; k < 4; k++) {
            if (sf[k] >= lo && sf[k] <= hi) {
                int pos = atomicAdd(&wcount, 1);
                if (pos < SLOTS) g_cand[(size_t)row * SLOTS + pos] = (uint16_t)(idx0 + k);
            }
        }
        __syncthreads();
        if (t == 0) {
            int tt = 0;
#pragma unroll
            for (int i = 0; i < 8; i++) tt += wsum[i];
            sh_csure = tt;
        }
        __syncthreads();
    }

    const bool overflow = wcount > SLOTS;
    if (!overflow) {
        if (t == 0) {
            g_cnt[row]   = wcount;
            g_need2[row] = K_TOP - sh_csure;
        }
        // write O: sure-ins get x, window positions 0 (patched later), rest 0
        float4 o;
        o.x = (sf[0] > hi) ? xv.x : 0.0f;
        o.y = (sf[1] > hi) ? xv.y : 0.0f;
        o.z = (sf[2] > hi) ? xv.z : 0.0f;
        o.w = (sf[3] > hi) ? xv.w : 0.0f;
        ((float4*)(O + base))[t] = o;
    } else {
        // rare fallback: select by approx value with index tie-break at T
        const uint32_t T = sh_T;
        // needT = K - count(>T)
        int cg = (vv[0] > T) + (vv[1] > T) + (vv[2] > T) + (vv[3] > T);
#pragma unroll
        for (int off = 16; off; off >>= 1) cg += __shfl_down_sync(0xffffffffu, cg, off);
        if (lane == 0) wsum[wrp] = cg;
        __syncthreads();
        int totg = 0;
#pragma unroll
        for (int i = 0; i < 8; i++) totg += wsum[i];
        const int needT = K_TOP - totg;
        __syncthreads();
        // index-ordered rank among == T
        const int e0 = (vv[0] == T), e1 = (vv[1] == T), e2 = (vv[2] == T), e3 = (vv[3] == T);
        const int cnt4 = e0 + e1 + e2 + e3;
        int incl = cnt4;
#pragma unroll
        for (int off = 1; off < 32; off <<= 1) {
            int v = __shfl_up_sync(0xffffffffu, incl, off);
            if (lane >= off) incl += v;
        }
        if (lane == 31) wsum[wrp] = incl;
        __syncthreads();
        if (t == 0) {
            int ssum = 0;
#pragma unroll
            for (int i = 0; i < 8; i++) { int v = wsum[i]; wsum[i] = ssum; ssum += v; }
            g_cnt[row] = 0;   // patch kernel skips this row
        }
        __syncthreads();
        int rank = wsum[wrp] + (incl - cnt4);
        float4 o;
        const bool s0 = (vv[0] > T) || (e0 && rank < needT); rank += e0;
        const bool s1 = (vv[1] > T) || (e1 && rank < needT); rank += e1;
        const bool s2 = (vv[2] > T) || (e2 && rank < needT); rank += e2;
        const bool s3 = (vv[3] > T) || (e3 && rank < needT);
        o.x = s0 ? xv.x : 0.0f;
        o.y = s1 ? xv.y : 0.0f;
        o.z = s2 ? xv.z : 0.0f;
        o.w = s3 ? xv.w : 0.0f;
        ((float4*)(O + base))[t] = o;
    }
}

// ============================ kernel 2: patch ================================
// One block per row; exits immediately if no window candidates. Exact fp32
// rescoring of candidates (one warp each), rank by (score desc, idx asc),
// write selected x values into O.
__global__ __launch_bounds__(128)
void topk_patch_kernel(const float* __restrict__ X, const float* __restrict__ W,
                       const float* __restrict__ bias, float* __restrict__ O) {
    const int row = blockIdx.x;
    const int cnt = g_cnt[row];
    if (cnt == 0) return;

    const int t = threadIdx.x;
    const int lane = t & 31, wrp = t >> 5;
    const size_t base = (size_t)row * D_DIM;
    const int need2 = g_need2[row];

    __shared__ float wcf[SLOTS];
    __shared__ int   wci[SLOTS];

    if (t < cnt) wci[t] = (int)g_cand[(size_t)row * SLOTS + t];
    __syncthreads();

    const float4* xr = (const float4*)(X + base);
    for (int c = wrp; c < cnt; c += 4) {
        const int e = wci[c];
        const float4* wr = (const float4*)(W + (size_t)e * D_DIM);
        float a0 = 0.0f, a1 = 0.0f, a2 = 0.0f, a3 = 0.0f;
#pragma unroll
        for (int j = 0; j < 8; j++) {
            const int i4 = j * 32 + lane;
            const float4 wv = wr[i4];
            const float4 xq = xr[i4];
            a0 = fmaf(xq.x, wv.x, a0);
            a1 = fmaf(xq.y, wv.y, a1);
            a2 = fmaf(xq.z, wv.z, a2);
            a3 = fmaf(xq.w, wv.w, a3);
        }
        float acc = (a0 + a1) + (a2 + a3);
#pragma unroll
        for (int off = 16; off; off >>= 1) acc += __shfl_down_sync(0xffffffffu, acc, off);
        if (lane == 0) wcf[c] = sigmoid_acc(acc + bias[e]);
    }
    __syncthreads();

    if (t < cnt) {
        const float f = wcf[t];
        const int  id = wci[t];
        int r = 0;
        for (int j = 0; j < cnt; j++) {
            const float fj = wcf[j];
            r += (fj > f) || (fj == f && wci[j] < id);
        }
        if (r < need2) O[base + id] = X[base + id];
    }
}

// ============================ launch =========================================
extern "C" void kernel_launch(void* const* d_in, const int* in_sizes, int n_in,
                              void* d_out, int out_size) {
    const float* X = (const float*)d_in[0];  // [N, 1024]
    const float* W = (const float*)d_in[1];  // [1024, 1024]
    const float* b = (const float*)d_in[2];  // [1024]
    float* out = (float*)d_out;              // [2, N, 1024]

    const int N = in_sizes[0] / D_DIM;
    float* S = out + (size_t)N * D_DIM;

    uint16_t *wh, *xh;
    cudaGetSymbolAddress((void**)&wh, g_Wh);
    cudaGetSymbolAddress((void**)&xh, g_Xh);

    cudaFuncSetAttribute(gemm_hmma_kernel,
                         cudaFuncAttributeMaxDynamicSharedMemorySize, SMEM_GEMM);

    split1_kernel<<<D_DIM * D_DIM / 8 / 256, 256>>>(W, wh);
    split1_kernel<<<(int)((size_t)N * D_DIM / 8 / 256), 256>>>(X, xh);
    gemm_hmma_kernel<<<dim3(D_DIM / 128, N / 64), 256, SMEM_GEMM>>>(b, S);
    topk_select_kernel<<<N, 256>>>(X, S, out);
    topk_patch_kernel<<<N, 128>>>(X, W, b, out);
}